// round 11
// baseline (speedup 1.0000x reference)
#include <cuda_runtime.h>
#include <cuda_bf16.h>
#include <cuda_fp16.h>
#include <stdint.h>

// H3TCSNetwork, mma.sync path. R11: occupancy push.
// m32n32 warp tile (acc 32 regs) + ping-pong fp16 activation planes
// (1 barrier/layer) + bias_h via __ldg  =>  3 CTAs/SM (occ ~37%).

#define NTHREADS 256
#define MROWS    64
#define HID      256
#define NOUT     2695
#define APITCH   264                 // fp16 elems per smem plane row (528 B)

#define PACK_HIDW  16384             // 64 * 256 uint2 per hidden layer
#define HID_U32    (3*PACK_HIDW*2)
#define PACK_HEAD  172480            // 64 * 2695 uint2
#define PACK_U32   (HID_U32 + PACK_HEAD*2)

__device__ uint32_t g_pack[PACK_U32];

// ---------------- helpers ----------------
__device__ __forceinline__ uint32_t smem_u32(const void* p){
    return (uint32_t)__cvta_generic_to_shared(p);
}
__device__ __forceinline__ uint32_t pack2h(float lo, float hi){
    uint32_t r;
    asm("cvt.rn.f16x2.f32 %0, %1, %2;" : "=r"(r) : "f"(hi), "f"(lo));
    return r;
}
__device__ __forceinline__ float silu_f(float v){
    return __fdividef(v, 1.0f + __expf(-v));
}
__device__ __forceinline__ void ldsm_x4(uint32_t a[4], uint32_t addr){
    asm volatile("ldmatrix.sync.aligned.m8n8.x4.shared.b16 {%0,%1,%2,%3}, [%4];"
                 : "=r"(a[0]), "=r"(a[1]), "=r"(a[2]), "=r"(a[3]) : "r"(addr));
}
__device__ __forceinline__ void mma_f16(float c[4], const uint32_t a[4],
                                        uint32_t b0, uint32_t b1){
    asm volatile("mma.sync.aligned.m16n8k16.row.col.f32.f16.f16.f32 "
                 "{%0,%1,%2,%3}, {%4,%5,%6,%7}, {%8,%9}, {%0,%1,%2,%3};"
                 : "+f"(c[0]), "+f"(c[1]), "+f"(c[2]), "+f"(c[3])
                 : "r"(a[0]), "r"(a[1]), "r"(a[2]), "r"(a[3]), "r"(b0), "r"(b1));
}

// ---------------- weight pack kernel ----------------
// uint2 at [(s*4+q)*N + n]:
//   x = f16x2(W[k0][n], W[k0+1][n]),  y = f16x2(W[k0+8][n], W[k0+9][n]),
//   k0 = s*16 + q*2.
#define PACK_N (3*PACK_HIDW + PACK_HEAD)
__global__ void pack_weights(const float* __restrict__ W1, const float* __restrict__ W2,
                             const float* __restrict__ W3, const float* __restrict__ Wh)
{
    int idx = blockIdx.x * blockDim.x + threadIdx.x;
    if (idx >= PACK_N) return;
    if (idx < 3*PACK_HIDW){
        const float* W; uint2* P; int li = idx;
        if      (idx < PACK_HIDW)   { W = W1; P = (uint2*)g_pack; }
        else if (idx < 2*PACK_HIDW) { W = W2; P = (uint2*)g_pack + PACK_HIDW;   li -= PACK_HIDW; }
        else                        { W = W3; P = (uint2*)g_pack + 2*PACK_HIDW; li -= 2*PACK_HIDW; }
        int n  = li & 255;
        int sq = li >> 8;
        int q  = sq & 3, s = sq >> 2;
        int k0 = s * 16 + q * 2;
        uint2 v;
        v.x = pack2h(W[(size_t)k0     * HID + n], W[(size_t)(k0+1) * HID + n]);
        v.y = pack2h(W[(size_t)(k0+8) * HID + n], W[(size_t)(k0+9) * HID + n]);
        P[li] = v;
    } else {
        int li = idx - 3*PACK_HIDW;
        int n  = li % NOUT;
        int sq = li / NOUT;
        int q  = sq & 3, s = sq >> 2;
        int k0 = s * 16 + q * 2;
        uint2 v;
        v.x = pack2h(Wh[(size_t)k0     * NOUT + n], Wh[(size_t)(k0+1) * NOUT + n]);
        v.y = pack2h(Wh[(size_t)(k0+8) * NOUT + n], Wh[(size_t)(k0+9) * NOUT + n]);
        ((uint2*)(g_pack + HID_U32))[li] = v;
    }
}

// ---------------- warp GEMM (fp16 1-term, m32n32 tile, 2-deep B ring) -------
// Each kstep: ldsm A -> MMA(current b) -> refill b for kstep s+2.
template<bool GUARD>
__device__ __forceinline__ void warp_gemm_f16(uint32_t abase,
                                              const uint2* __restrict__ P, int Nmat,
                                              int n0, int lane, float acc[2][4][4])
{
    const int q  = lane & 3;
    const int nl = lane >> 2;
    bool ok[4];
    #pragma unroll
    for (int nt = 0; nt < 4; nt++)
        ok[nt] = !GUARD || (n0 + nt*8 + nl) < Nmat;

    const uint2* p = P + (size_t)q * Nmat + n0 + nl;
    uint2 b0[4], b1[4];
    #pragma unroll
    for (int nt = 0; nt < 4; nt++) b0[nt] = ok[nt] ? p[nt*8] : make_uint2(0,0);
    p += 4*Nmat;
    #pragma unroll
    for (int nt = 0; nt < 4; nt++) b1[nt] = ok[nt] ? p[nt*8] : make_uint2(0,0);
    p += 4*Nmat;

    #pragma unroll 1
    for (int s = 0; s < 16; s += 2){
        {
            uint32_t a[2][4];
            #pragma unroll
            for (int mt = 0; mt < 2; mt++)
                ldsm_x4(a[mt], abase + (uint32_t)(mt*16)*(APITCH*2) + s*32);
            #pragma unroll
            for (int mt = 0; mt < 2; mt++)
                #pragma unroll
                for (int nt = 0; nt < 4; nt++)
                    mma_f16(acc[mt][nt], a[mt], b0[nt].x, b0[nt].y);
            if (s < 14){
                #pragma unroll
                for (int nt = 0; nt < 4; nt++)
                    if (ok[nt]) b0[nt] = p[nt*8];
                p += 4*Nmat;
            }
        }
        {
            uint32_t a[2][4];
            #pragma unroll
            for (int mt = 0; mt < 2; mt++)
                ldsm_x4(a[mt], abase + (uint32_t)(mt*16)*(APITCH*2) + (s+1)*32);
            #pragma unroll
            for (int mt = 0; mt < 2; mt++)
                #pragma unroll
                for (int nt = 0; nt < 4; nt++)
                    mma_f16(acc[mt][nt], a[mt], b1[nt].x, b1[nt].y);
            if (s < 13){
                #pragma unroll
                for (int nt = 0; nt < 4; nt++)
                    if (ok[nt]) b1[nt] = p[nt*8];
                p += 4*Nmat;
            }
        }
    }
}

__device__ __forceinline__ float hsel(int col, float l, float r, float n){
    if (col < 1225) return 1.0f;
    if (col < 1715) return l;
    if (col < 2205) return r;
    return n;
}

// ---------------- main fused kernel ----------------
__global__ __launch_bounds__(NTHREADS, 3)
void h3tcs_mma_kernel(const float* __restrict__ x,
                      const float* __restrict__ W0, const float* __restrict__ b0,
                      const float* __restrict__ b1, const float* __restrict__ b2,
                      const float* __restrict__ b3, const float* __restrict__ bh,
                      float* __restrict__ out)
{
    extern __shared__ char smem[];
    __half* p0    = (__half*)smem;                    // plane 0
    __half* p1    = p0 + MROWS*APITCH;                // plane 1
    float* xs     = (float*)(p1 + MROWS*APITCH);
    float* scl    = xs  + MROWS*7;
    float* scr    = scl + MROWS;
    float* scn    = scr + MROWS;
    float* bias_s = scn + MROWS;                      // 3*256

    const int tid  = threadIdx.x;
    const int lane = tid & 31;
    const int wid  = tid >> 5;
    const int wm   = wid >> 2;           // m half: rows wm*32..wm*32+31
    const int wn   = wid & 3;            // n quarter within 128-col pass
    const int r0   = blockIdx.x * MROWS;

    for (int i = tid; i < MROWS*7; i += NTHREADS) xs[i] = x[(size_t)r0*7 + i];
    bias_s[tid]       = b1[tid];
    bias_s[256 + tid] = b2[tid];
    bias_s[512 + tid] = b3[tid];
    __syncthreads();

    if (tid < MROWS){
        float lam = xs[tid*7];
        float s = 1.0f / (1.0f + __expf(lam * (-5.0f/0.15f)));
        scl[tid] = 1.0f - s;
        scr[tid] = s;
        float t = lam * 5.0f;
        scn[tid] = __expf(-t*t);
    }

    // ---- layer 0 (7 -> 256), fp32 FFMA, fp16 store to plane 0 ----
    {
        int j = tid;
        float w0r[7];
        #pragma unroll
        for (int k = 0; k < 7; k++) w0r[k] = W0[k*HID + j];
        float bj = b0[j];
        for (int r = 0; r < MROWS; r++){
            float v = bj;
            #pragma unroll
            for (int k = 0; k < 7; k++) v = fmaf(xs[r*7 + k], w0r[k], v);
            p0[r*APITCH + j] = __float2half(silu_f(v));
        }
    }
    __syncthreads();

    const int sub = lane >> 3;
    const int rowin = (lane & 7) + (sub & 1) * 8;
    const int colin = (sub >> 1) * 8;
    const uint32_t arow = ((uint32_t)(wm*32 + rowin) * APITCH + colin) * 2;
    const uint32_t abase0 = smem_u32(p0) + arow;
    const uint32_t abase1 = smem_u32(p1) + arow;

    // ---- hidden layers 1..3: fp16 1-term, ping-pong planes, 1 barrier/layer -
    #pragma unroll 1
    for (int L = 0; L < 3; L++){
        const uint32_t abase = (L & 1) ? abase1 : abase0;   // L0:p0->p1, L1:p1->p0, L2:p0->p1
        __half* dst = (L & 1) ? p0 : p1;
        const float* bs = bias_s + L*256;
        const uint2* Pw = (const uint2*)g_pack + L*PACK_HIDW;

        #pragma unroll 1
        for (int pass = 0; pass < 2; pass++){
            int nb = pass*128 + wn*32;
            float acc[2][4][4];
            #pragma unroll
            for (int a = 0; a < 2; a++)
                #pragma unroll
                for (int b = 0; b < 4; b++)
                    #pragma unroll
                    for (int c = 0; c < 4; c++) acc[a][b][c] = 0.0f;

            warp_gemm_f16<false>(abase, Pw, HID, nb, lane, acc);

            #pragma unroll
            for (int mt = 0; mt < 2; mt++){
                int rb = wm*32 + mt*16 + (lane >> 2);
                #pragma unroll
                for (int nt = 0; nt < 4; nt++){
                    int cb = nb + nt*8 + (lane & 3)*2;
                    float bb0 = bs[cb], bb1 = bs[cb+1];
                    float v0 = silu_f(acc[mt][nt][0] + bb0);
                    float v1 = silu_f(acc[mt][nt][1] + bb1);
                    *(uint32_t*)&dst[rb*APITCH + cb] = pack2h(v0, v1);
                    float v2 = silu_f(acc[mt][nt][2] + bb0);
                    float v3 = silu_f(acc[mt][nt][3] + bb1);
                    *(uint32_t*)&dst[(rb+8)*APITCH + cb] = pack2h(v2, v3);
                }
            }
        }
        __syncthreads();       // dst plane complete before next layer reads it
    }

    // ---- head (256 -> 2695): reads plane 1, 22 chunks of 128 cols ----
    const uint2* Ph = (const uint2*)(g_pack + HID_U32);
    #pragma unroll 1
    for (int nc = 0; nc < 22; nc++){
        int nbase = nc*128 + wn*32;
        float acc[2][4][4];
        #pragma unroll
        for (int a = 0; a < 2; a++)
            #pragma unroll
            for (int b = 0; b < 4; b++)
                #pragma unroll
                for (int c = 0; c < 4; c++) acc[a][b][c] = 0.0f;

        if (nc < 21) warp_gemm_f16<false>(abase1, Ph, NOUT, nbase, lane, acc);
        else         warp_gemm_f16<true >(abase1, Ph, NOUT, nbase, lane, acc);

        #pragma unroll
        for (int mt = 0; mt < 2; mt++){
            int rr = wm*32 + mt*16 + (lane >> 2);
            float l0 = scl[rr],   rv0 = scr[rr],   n0s = scn[rr];
            float l1 = scl[rr+8], rv1 = scr[rr+8], n1s = scn[rr+8];
            #pragma unroll
            for (int nt = 0; nt < 4; nt++){
                int cb = nbase + nt*8 + (lane & 3)*2;
                if (cb < NOUT){
                    float bb0 = __ldg(&bh[cb]);
                    float s0 = hsel(cb, l0, rv0, n0s);
                    float s1 = hsel(cb, l1, rv1, n1s);
                    out[(size_t)(r0+rr)   * NOUT + cb] = (acc[mt][nt][0] + bb0) * s0;
                    out[(size_t)(r0+rr+8) * NOUT + cb] = (acc[mt][nt][2] + bb0) * s1;
                    if (cb + 1 < NOUT){
                        float bb1 = __ldg(&bh[cb+1]);
                        float t0 = hsel(cb+1, l0, rv0, n0s);
                        float t1 = hsel(cb+1, l1, rv1, n1s);
                        out[(size_t)(r0+rr)   * NOUT + cb+1] = (acc[mt][nt][1] + bb1) * t0;
                        out[(size_t)(r0+rr+8) * NOUT + cb+1] = (acc[mt][nt][3] + bb1) * t1;
                    }
                }
            }
        }
    }
}

// ---------------- launch ----------------
#define SMEM_BYTES (2*MROWS*APITCH*2 + (MROWS*7 + 3*MROWS + 3*256)*4)

extern "C" void kernel_launch(void* const* d_in, const int* in_sizes, int n_in,
                              void* d_out, int out_size)
{
    const float* x  = (const float*)d_in[0];
    const float* W0 = (const float*)d_in[1];
    const float* b0 = (const float*)d_in[2];
    const float* W1 = (const float*)d_in[3];
    const float* b1 = (const float*)d_in[4];
    const float* W2 = (const float*)d_in[5];
    const float* b2 = (const float*)d_in[6];
    const float* W3 = (const float*)d_in[7];
    const float* b3 = (const float*)d_in[8];
    const float* Wh = (const float*)d_in[9];
    const float* bh = (const float*)d_in[10];
    float* out = (float*)d_out;

    int B = in_sizes[0] / 7;

    cudaFuncSetAttribute(h3tcs_mma_kernel,
                         cudaFuncAttributeMaxDynamicSharedMemorySize, SMEM_BYTES);

    pack_weights<<<(PACK_N + 255)/256, 256>>>(W1, W2, W3, Wh);
    h3tcs_mma_kernel<<<B / MROWS, NTHREADS, SMEM_BYTES>>>(x, W0, b0, b1, b2, b3, bh, out);
}

// round 12
// speedup vs baseline: 1.3388x; 1.3388x over previous
#include <cuda_runtime.h>
#include <cuda_bf16.h>
#include <cuda_fp16.h>
#include <stdint.h>

// H3TCSNetwork, mma.sync path. R12 = R10 (752us) with software-pipelined A:
// ldsm interleaved with previous tile's MMA group, 2 rotating A buffers,
// cross-kstep mt0 prefetch. Everything else identical to R10.

#define NTHREADS 256
#define MROWS    64
#define HID      256
#define NOUT     2695
#define APITCH   264                 // fp16 elems per smem plane row (528 B)

#define PACK_HIDW  16384             // 64 * 256 uint2 per hidden layer
#define HID_U32    (3*PACK_HIDW*2)
#define PACK_HEAD  172480            // 64 * 2695 uint2
#define PACK_U32   (HID_U32 + PACK_HEAD*2)

__device__ uint32_t g_pack[PACK_U32];

// ---------------- helpers ----------------
__device__ __forceinline__ uint32_t smem_u32(const void* p){
    return (uint32_t)__cvta_generic_to_shared(p);
}
__device__ __forceinline__ uint32_t pack2h(float lo, float hi){
    uint32_t r;
    asm("cvt.rn.f16x2.f32 %0, %1, %2;" : "=r"(r) : "f"(hi), "f"(lo));
    return r;
}
__device__ __forceinline__ float silu_f(float v){
    return __fdividef(v, 1.0f + __expf(-v));
}
__device__ __forceinline__ void ldsm_x4(uint32_t a[4], uint32_t addr){
    asm volatile("ldmatrix.sync.aligned.m8n8.x4.shared.b16 {%0,%1,%2,%3}, [%4];"
                 : "=r"(a[0]), "=r"(a[1]), "=r"(a[2]), "=r"(a[3]) : "r"(addr));
}
__device__ __forceinline__ void mma_f16(float c[4], const uint32_t a[4],
                                        uint32_t b0, uint32_t b1){
    asm volatile("mma.sync.aligned.m16n8k16.row.col.f32.f16.f16.f32 "
                 "{%0,%1,%2,%3}, {%4,%5,%6,%7}, {%8,%9}, {%0,%1,%2,%3};"
                 : "+f"(c[0]), "+f"(c[1]), "+f"(c[2]), "+f"(c[3])
                 : "r"(a[0]), "r"(a[1]), "r"(a[2]), "r"(a[3]), "r"(b0), "r"(b1));
}

// ---------------- weight pack kernel ----------------
// uint2 at [(s*4+q)*N + n]:
//   x = f16x2(W[k0][n], W[k0+1][n]),  y = f16x2(W[k0+8][n], W[k0+9][n]),
//   k0 = s*16 + q*2.
#define PACK_N (3*PACK_HIDW + PACK_HEAD)
__global__ void pack_weights(const float* __restrict__ W1, const float* __restrict__ W2,
                             const float* __restrict__ W3, const float* __restrict__ Wh)
{
    int idx = blockIdx.x * blockDim.x + threadIdx.x;
    if (idx >= PACK_N) return;
    if (idx < 3*PACK_HIDW){
        const float* W; uint2* P; int li = idx;
        if      (idx < PACK_HIDW)   { W = W1; P = (uint2*)g_pack; }
        else if (idx < 2*PACK_HIDW) { W = W2; P = (uint2*)g_pack + PACK_HIDW;   li -= PACK_HIDW; }
        else                        { W = W3; P = (uint2*)g_pack + 2*PACK_HIDW; li -= 2*PACK_HIDW; }
        int n  = li & 255;
        int sq = li >> 8;
        int q  = sq & 3, s = sq >> 2;
        int k0 = s * 16 + q * 2;
        uint2 v;
        v.x = pack2h(W[(size_t)k0     * HID + n], W[(size_t)(k0+1) * HID + n]);
        v.y = pack2h(W[(size_t)(k0+8) * HID + n], W[(size_t)(k0+9) * HID + n]);
        P[li] = v;
    } else {
        int li = idx - 3*PACK_HIDW;
        int n  = li % NOUT;
        int sq = li / NOUT;
        int q  = sq & 3, s = sq >> 2;
        int k0 = s * 16 + q * 2;
        uint2 v;
        v.x = pack2h(Wh[(size_t)k0     * NOUT + n], Wh[(size_t)(k0+1) * NOUT + n]);
        v.y = pack2h(Wh[(size_t)(k0+8) * NOUT + n], Wh[(size_t)(k0+9) * NOUT + n]);
        ((uint2*)(g_pack + HID_U32))[li] = v;
    }
}

#define MMA4(accrow, a, b) \
    do { \
        mma_f16((accrow)[0], a, (b)[0].x, (b)[0].y); \
        mma_f16((accrow)[1], a, (b)[1].x, (b)[1].y); \
        mma_f16((accrow)[2], a, (b)[2].x, (b)[2].y); \
        mma_f16((accrow)[3], a, (b)[3].x, (b)[3].y); \
    } while(0)

// ------- unified warp GEMM (fp16 1-term, 64x32 tile, pipelined A + B ring) ---
template<bool GUARD>
__device__ __forceinline__ void warp_gemm_f16(uint32_t abase,
                                              const uint2* __restrict__ P, int Nmat,
                                              int n0, int lane, float acc[4][4][4])
{
    const int q  = lane & 3;
    const int nl = lane >> 2;
    bool ok[4];
    #pragma unroll
    for (int nt = 0; nt < 4; nt++)
        ok[nt] = !GUARD || (n0 + nt*8 + nl) < Nmat;

    const uint2* p = P + (size_t)q * Nmat + n0 + nl;
    uint2 b0[4], b1[4];
    #pragma unroll
    for (int nt = 0; nt < 4; nt++) b0[nt] = ok[nt] ? p[nt*8] : make_uint2(0,0);
    p += 4*Nmat;
    #pragma unroll
    for (int nt = 0; nt < 4; nt++) b1[nt] = ok[nt] ? p[nt*8] : make_uint2(0,0);
    p += 4*Nmat;

    const uint32_t MT = 16u * (APITCH*2);      // 16 rows
    uint32_t a0[4], a1[4];
    ldsm_x4(a0, abase);                        // mt0, kstep 0

    #pragma unroll 1
    for (int s = 0; s < 16; s += 2){
        const uint32_t bs = abase + (uint32_t)s * 32;
        // ---- kstep s (consumes b0; a0 holds mt0) ----
        ldsm_x4(a1, bs + MT);                  // mt1
        MMA4(acc[0], a0, b0);
        ldsm_x4(a0, bs + 2*MT);                // mt2
        MMA4(acc[1], a1, b0);
        ldsm_x4(a1, bs + 3*MT);                // mt3
        MMA4(acc[2], a0, b0);
        ldsm_x4(a0, bs + 32);                  // mt0, kstep s+1
        MMA4(acc[3], a1, b0);
        if (s < 14){
            #pragma unroll
            for (int nt = 0; nt < 4; nt++)
                if (ok[nt]) b0[nt] = p[nt*8];
            p += 4*Nmat;
        }
        // ---- kstep s+1 (consumes b1; a0 holds mt0) ----
        ldsm_x4(a1, bs + 32 + MT);
        MMA4(acc[0], a0, b1);
        ldsm_x4(a0, bs + 32 + 2*MT);
        MMA4(acc[1], a1, b1);
        ldsm_x4(a1, bs + 32 + 3*MT);
        MMA4(acc[2], a0, b1);
        ldsm_x4(a0, bs + 64);                  // mt0, kstep s+2 (s=14: reads row pad, in-plane)
        MMA4(acc[3], a1, b1);
        if (s < 13){
            #pragma unroll
            for (int nt = 0; nt < 4; nt++)
                if (ok[nt]) b1[nt] = p[nt*8];
            p += 4*Nmat;
        }
    }
}

__device__ __forceinline__ float hsel(int col, float l, float r, float n){
    if (col < 1225) return 1.0f;
    if (col < 1715) return l;
    if (col < 2205) return r;
    return n;
}

// ---------------- main fused kernel ----------------
__global__ __launch_bounds__(NTHREADS, 2)
void h3tcs_mma_kernel(const float* __restrict__ x,
                      const float* __restrict__ W0, const float* __restrict__ b0,
                      const float* __restrict__ b1, const float* __restrict__ b2,
                      const float* __restrict__ b3, const float* __restrict__ bh,
                      float* __restrict__ out)
{
    extern __shared__ char smem[];
    __half* pA    = (__half*)smem;                    // single fp16 plane
    float* xs     = (float*)(pA + MROWS*APITCH);
    float* scl    = xs  + MROWS*7;
    float* scr    = scl + MROWS;
    float* scn    = scr + MROWS;
    float* bias_s = scn + MROWS;                      // 3*256
    float* bias_h = bias_s + 3*256;                   // 2696

    const int tid  = threadIdx.x;
    const int lane = tid & 31;
    const int wid  = tid >> 5;
    const int r0   = blockIdx.x * MROWS;

    for (int i = tid; i < MROWS*7; i += NTHREADS) xs[i] = x[(size_t)r0*7 + i];
    bias_s[tid]       = b1[tid];
    bias_s[256 + tid] = b2[tid];
    bias_s[512 + tid] = b3[tid];
    for (int i = tid; i < NOUT; i += NTHREADS) bias_h[i] = bh[i];
    __syncthreads();

    if (tid < MROWS){
        float lam = xs[tid*7];
        float s = 1.0f / (1.0f + __expf(lam * (-5.0f/0.15f)));
        scl[tid] = 1.0f - s;
        scr[tid] = s;
        float t = lam * 5.0f;
        scn[tid] = __expf(-t*t);
    }

    // ---- layer 0 (7 -> 256), fp32 FFMA, fp16 store ----
    {
        int j = tid;
        float w0r[7];
        #pragma unroll
        for (int k = 0; k < 7; k++) w0r[k] = W0[k*HID + j];
        float bj = b0[j];
        for (int r = 0; r < MROWS; r++){
            float v = bj;
            #pragma unroll
            for (int k = 0; k < 7; k++) v = fmaf(xs[r*7 + k], w0r[k], v);
            pA[r*APITCH + j] = __float2half(silu_f(v));
        }
    }
    __syncthreads();

    const int sub = lane >> 3;
    const int rowin = (lane & 7) + (sub & 1) * 8;
    const int colin = (sub >> 1) * 8;
    const uint32_t abase = smem_u32(pA) + ((uint32_t)rowin * APITCH + colin) * 2;

    // ---- hidden layers 1..3: fp16 1-term, m64n32 per warp ----
    #pragma unroll 1
    for (int L = 0; L < 3; L++){
        float acc[4][4][4];
        #pragma unroll
        for (int a = 0; a < 4; a++)
            #pragma unroll
            for (int b = 0; b < 4; b++)
                #pragma unroll
                for (int c = 0; c < 4; c++) acc[a][b][c] = 0.0f;

        warp_gemm_f16<false>(abase, (const uint2*)g_pack + L*PACK_HIDW, HID,
                             wid*32, lane, acc);

        __syncthreads();            // all warps done READING plane
        const float* bs = bias_s + L*256;
        #pragma unroll
        for (int mt = 0; mt < 4; mt++){
            int rb = mt*16 + (lane >> 2);
            #pragma unroll
            for (int nt = 0; nt < 4; nt++){
                int cb = wid*32 + nt*8 + (lane & 3)*2;
                float bb0 = bs[cb], bb1 = bs[cb+1];
                float v0 = silu_f(acc[mt][nt][0] + bb0);
                float v1 = silu_f(acc[mt][nt][1] + bb1);
                *(uint32_t*)&pA[rb*APITCH + cb] = pack2h(v0, v1);
                float v2 = silu_f(acc[mt][nt][2] + bb0);
                float v3 = silu_f(acc[mt][nt][3] + bb1);
                *(uint32_t*)&pA[(rb+8)*APITCH + cb] = pack2h(v2, v3);
            }
        }
        __syncthreads();            // plane fully rewritten
    }

    // ---- head (256 -> 2695), fp16 1-term ----
    const uint2* Ph = (const uint2*)(g_pack + HID_U32);
    #pragma unroll 1
    for (int nc = 0; nc < 11; nc++){
        int nbase = nc*256 + wid*32;
        float acc[4][4][4];
        #pragma unroll
        for (int a = 0; a < 4; a++)
            #pragma unroll
            for (int b = 0; b < 4; b++)
                #pragma unroll
                for (int c = 0; c < 4; c++) acc[a][b][c] = 0.0f;

        if (nc < 10) warp_gemm_f16<false>(abase, Ph, NOUT, nbase, lane, acc);
        else         warp_gemm_f16<true >(abase, Ph, NOUT, nbase, lane, acc);

        #pragma unroll
        for (int mt = 0; mt < 4; mt++){
            int rr = mt*16 + (lane >> 2);
            float l0 = scl[rr],   rv0 = scr[rr],   n0s = scn[rr];
            float l1 = scl[rr+8], rv1 = scr[rr+8], n1s = scn[rr+8];
            #pragma unroll
            for (int nt = 0; nt < 4; nt++){
                int cb = nbase + nt*8 + (lane & 3)*2;
                if (cb < NOUT){
                    float bb0 = bias_h[cb];
                    float s0 = hsel(cb, l0, rv0, n0s);
                    float s1 = hsel(cb, l1, rv1, n1s);
                    out[(size_t)(r0+rr)   * NOUT + cb] = (acc[mt][nt][0] + bb0) * s0;
                    out[(size_t)(r0+rr+8) * NOUT + cb] = (acc[mt][nt][2] + bb0) * s1;
                    if (cb + 1 < NOUT){
                        float bb1 = bias_h[cb+1];
                        float t0 = hsel(cb+1, l0, rv0, n0s);
                        float t1 = hsel(cb+1, l1, rv1, n1s);
                        out[(size_t)(r0+rr)   * NOUT + cb+1] = (acc[mt][nt][1] + bb1) * t0;
                        out[(size_t)(r0+rr+8) * NOUT + cb+1] = (acc[mt][nt][3] + bb1) * t1;
                    }
                }
            }
        }
    }
}

// ---------------- launch ----------------
#define SMEM_BYTES (MROWS*APITCH*2 + (MROWS*7 + 3*MROWS + 3*256 + 2696)*4)

extern "C" void kernel_launch(void* const* d_in, const int* in_sizes, int n_in,
                              void* d_out, int out_size)
{
    const float* x  = (const float*)d_in[0];
    const float* W0 = (const float*)d_in[1];
    const float* b0 = (const float*)d_in[2];
    const float* W1 = (const float*)d_in[3];
    const float* b1 = (const float*)d_in[4];
    const float* W2 = (const float*)d_in[5];
    const float* b2 = (const float*)d_in[6];
    const float* W3 = (const float*)d_in[7];
    const float* b3 = (const float*)d_in[8];
    const float* Wh = (const float*)d_in[9];
    const float* bh = (const float*)d_in[10];
    float* out = (float*)d_out;

    int B = in_sizes[0] / 7;

    cudaFuncSetAttribute(h3tcs_mma_kernel,
                         cudaFuncAttributeMaxDynamicSharedMemorySize, SMEM_BYTES);

    pack_weights<<<(PACK_N + 255)/256, 256>>>(W1, W2, W3, Wh);
    h3tcs_mma_kernel<<<B / MROWS, NTHREADS, SMEM_BYTES>>>(x, W0, b0, b1, b2, b3, bh, out);
}

// round 13
// speedup vs baseline: 1.5084x; 1.1266x over previous
#include <cuda_runtime.h>
#include <cuda_bf16.h>
#include <cuda_fp16.h>
#include <stdint.h>

// H3TCSNetwork, mma.sync path. R13 = R12 with B staged via per-warp cp.async
// smem ring (depth 4, prefetch distance 3 ksteps) -- zero B registers, no
// long-scoreboard stall on B. A pipeline and everything else as R12/R10.

#define NTHREADS 256
#define MROWS    64
#define HID      256
#define NOUT     2695
#define APITCH   264                 // fp16 elems per smem plane row (528 B)

#define PACK_HIDW  16384             // 64 * 256 uint2 per hidden layer
#define HID_U32    (3*PACK_HIDW*2)
#define PACK_HEAD  172480            // 64 * 2695 uint2
#define PACK_U32   (HID_U32 + PACK_HEAD*2 + 512)   // +512 u32 pad for tail-chunk reads

__device__ uint32_t g_pack[PACK_U32];

// ---------------- helpers ----------------
__device__ __forceinline__ uint32_t smem_u32(const void* p){
    return (uint32_t)__cvta_generic_to_shared(p);
}
__device__ __forceinline__ uint32_t pack2h(float lo, float hi){
    uint32_t r;
    asm("cvt.rn.f16x2.f32 %0, %1, %2;" : "=r"(r) : "f"(hi), "f"(lo));
    return r;
}
__device__ __forceinline__ float silu_f(float v){
    return __fdividef(v, 1.0f + __expf(-v));
}
__device__ __forceinline__ void ldsm_x4(uint32_t a[4], uint32_t addr){
    asm volatile("ldmatrix.sync.aligned.m8n8.x4.shared.b16 {%0,%1,%2,%3}, [%4];"
                 : "=r"(a[0]), "=r"(a[1]), "=r"(a[2]), "=r"(a[3]) : "r"(addr));
}
__device__ __forceinline__ void mma_f16(float c[4], const uint32_t a[4],
                                        uint32_t b0, uint32_t b1){
    asm volatile("mma.sync.aligned.m16n8k16.row.col.f32.f16.f16.f32 "
                 "{%0,%1,%2,%3}, {%4,%5,%6,%7}, {%8,%9}, {%0,%1,%2,%3};"
                 : "+f"(c[0]), "+f"(c[1]), "+f"(c[2]), "+f"(c[3])
                 : "r"(a[0]), "r"(a[1]), "r"(a[2]), "r"(a[3]), "r"(b0), "r"(b1));
}
__device__ __forceinline__ void cp8(uint32_t dst, const void* src){
    asm volatile("cp.async.ca.shared.global [%0], [%1], 8;" :: "r"(dst), "l"(src));
}
#define CPC()  asm volatile("cp.async.commit_group;" ::: "memory")
#define CPW2() asm volatile("cp.async.wait_group 2;" ::: "memory")
__device__ __forceinline__ void lds64(uint32_t& x, uint32_t& y, uint32_t addr){
    asm volatile("ld.shared.v2.u32 {%0,%1}, [%2];" : "=r"(x), "=r"(y) : "r"(addr));
}

// ---------------- weight pack kernel ----------------
// uint2 at [(s*4+q)*N + n]:
//   x = f16x2(W[k0][n], W[k0+1][n]),  y = f16x2(W[k0+8][n], W[k0+9][n]),
//   k0 = s*16 + q*2.
#define PACK_N (3*PACK_HIDW + PACK_HEAD)
__global__ void pack_weights(const float* __restrict__ W1, const float* __restrict__ W2,
                             const float* __restrict__ W3, const float* __restrict__ Wh)
{
    int idx = blockIdx.x * blockDim.x + threadIdx.x;
    if (idx >= PACK_N) return;
    if (idx < 3*PACK_HIDW){
        const float* W; uint2* P; int li = idx;
        if      (idx < PACK_HIDW)   { W = W1; P = (uint2*)g_pack; }
        else if (idx < 2*PACK_HIDW) { W = W2; P = (uint2*)g_pack + PACK_HIDW;   li -= PACK_HIDW; }
        else                        { W = W3; P = (uint2*)g_pack + 2*PACK_HIDW; li -= 2*PACK_HIDW; }
        int n  = li & 255;
        int sq = li >> 8;
        int q  = sq & 3, s = sq >> 2;
        int k0 = s * 16 + q * 2;
        uint2 v;
        v.x = pack2h(W[(size_t)k0     * HID + n], W[(size_t)(k0+1) * HID + n]);
        v.y = pack2h(W[(size_t)(k0+8) * HID + n], W[(size_t)(k0+9) * HID + n]);
        P[li] = v;
    } else {
        int li = idx - 3*PACK_HIDW;
        int n  = li % NOUT;
        int sq = li / NOUT;
        int q  = sq & 3, s = sq >> 2;
        int k0 = s * 16 + q * 2;
        uint2 v;
        v.x = pack2h(Wh[(size_t)k0     * NOUT + n], Wh[(size_t)(k0+1) * NOUT + n]);
        v.y = pack2h(Wh[(size_t)(k0+8) * NOUT + n], Wh[(size_t)(k0+9) * NOUT + n]);
        ((uint2*)(g_pack + HID_U32))[li] = v;
    }
}

#define MMA4(accrow, a, b) \
    do { \
        mma_f16((accrow)[0], a, (b)[0].x, (b)[0].y); \
        mma_f16((accrow)[1], a, (b)[1].x, (b)[1].y); \
        mma_f16((accrow)[2], a, (b)[2].x, (b)[2].y); \
        mma_f16((accrow)[3], a, (b)[3].x, (b)[3].y); \
    } while(0)

// ------- warp GEMM: fp16 1-term, 64x32 tile, B via cp.async ring (depth 4) ---
// Groups: prologue commits k0..k2; body kstep s commits k(s+3) (or empty) =>
// at top of kstep s, wait_group 2 completes exactly group k_s.
__device__ __forceinline__ void warp_gemm_cp(uint32_t abase, uint32_t bring,
                                             const uint2* __restrict__ P, int Nmat,
                                             int n0, int lane, float acc[4][4][4])
{
    const int q  = lane & 3;
    const int nl = lane >> 2;
    const uint2* src = P + (size_t)q * Nmat + n0 + nl;
    const uint32_t dlane = bring + (uint32_t)lane * 8u;

    #pragma unroll
    for (int s = 0; s < 3; s++){
        #pragma unroll
        for (int nt = 0; nt < 4; nt++)
            cp8(dlane + (uint32_t)s*1024u + (uint32_t)nt*256u, src + nt*8);
        CPC();
        src += 4*Nmat;
    }

    const uint32_t MT = 16u*(APITCH*2);
    uint32_t a0[4], a1[4];
    ldsm_x4(a0, abase);                        // mt0, kstep 0

    #pragma unroll 1
    for (int s = 0; s < 16; s++){
        CPW2();                                // slot s ready
        const uint32_t slot = dlane + (uint32_t)(s & 3)*1024u;
        uint2 b[4];
        lds64(b[0].x, b[0].y, slot);
        lds64(b[1].x, b[1].y, slot + 256u);
        lds64(b[2].x, b[2].y, slot + 512u);
        lds64(b[3].x, b[3].y, slot + 768u);

        const uint32_t bs = abase + (uint32_t)s * 32u;
        ldsm_x4(a1, bs + MT);                  // mt1
        MMA4(acc[0], a0, b);
        ldsm_x4(a0, bs + 2*MT);                // mt2
        MMA4(acc[1], a1, b);
        ldsm_x4(a1, bs + 3*MT);                // mt3
        MMA4(acc[2], a0, b);
        ldsm_x4(a0, bs + 32u);                 // mt0, kstep s+1 (s=15: row pad, in-plane)
        MMA4(acc[3], a1, b);

        if (s < 13){                           // stage kstep s+3
            #pragma unroll
            for (int nt = 0; nt < 4; nt++)
                cp8(dlane + (uint32_t)((s+3) & 3)*1024u + (uint32_t)nt*256u, src + nt*8);
            src += 4*Nmat;
        }
        CPC();                                 // commit (possibly empty) every kstep
    }
}

__device__ __forceinline__ float hsel(int col, float l, float r, float n){
    if (col < 1225) return 1.0f;
    if (col < 1715) return l;
    if (col < 2205) return r;
    return n;
}

// ---------------- main fused kernel ----------------
__global__ __launch_bounds__(NTHREADS, 2)
void h3tcs_mma_kernel(const float* __restrict__ x,
                      const float* __restrict__ W0, const float* __restrict__ b0,
                      const float* __restrict__ b1, const float* __restrict__ b2,
                      const float* __restrict__ b3, const float* __restrict__ bh,
                      float* __restrict__ out)
{
    extern __shared__ char smem[];
    char*   ringc = smem;                             // 8 warps * 4KB = 32KB (16B aligned)
    __half* pA    = (__half*)(smem + 8*4096);         // fp16 activation plane
    float* xs     = (float*)(pA + MROWS*APITCH);
    float* scl    = xs  + MROWS*7;
    float* scr    = scl + MROWS;
    float* scn    = scr + MROWS;
    float* bias_s = scn + MROWS;                      // 3*256
    float* bias_h = bias_s + 3*256;                   // 2696

    const int tid  = threadIdx.x;
    const int lane = tid & 31;
    const int wid  = tid >> 5;
    const int r0   = blockIdx.x * MROWS;
    const uint32_t bring = smem_u32(ringc) + (uint32_t)wid * 4096u;

    for (int i = tid; i < MROWS*7; i += NTHREADS) xs[i] = x[(size_t)r0*7 + i];
    bias_s[tid]       = b1[tid];
    bias_s[256 + tid] = b2[tid];
    bias_s[512 + tid] = b3[tid];
    for (int i = tid; i < NOUT; i += NTHREADS) bias_h[i] = bh[i];
    __syncthreads();

    if (tid < MROWS){
        float lam = xs[tid*7];
        float s = 1.0f / (1.0f + __expf(lam * (-5.0f/0.15f)));
        scl[tid] = 1.0f - s;
        scr[tid] = s;
        float t = lam * 5.0f;
        scn[tid] = __expf(-t*t);
    }

    // ---- layer 0 (7 -> 256), fp32 FFMA, fp16 store ----
    {
        int j = tid;
        float w0r[7];
        #pragma unroll
        for (int k = 0; k < 7; k++) w0r[k] = W0[k*HID + j];
        float bj = b0[j];
        for (int r = 0; r < MROWS; r++){
            float v = bj;
            #pragma unroll
            for (int k = 0; k < 7; k++) v = fmaf(xs[r*7 + k], w0r[k], v);
            pA[r*APITCH + j] = __float2half(silu_f(v));
        }
    }
    __syncthreads();

    const int sub = lane >> 3;
    const int rowin = (lane & 7) + (sub & 1) * 8;
    const int colin = (sub >> 1) * 8;
    const uint32_t abase = smem_u32(pA) + ((uint32_t)rowin * APITCH + colin) * 2;

    // ---- hidden layers 1..3: fp16 1-term, m64n32 per warp ----
    #pragma unroll 1
    for (int L = 0; L < 3; L++){
        float acc[4][4][4];
        #pragma unroll
        for (int a = 0; a < 4; a++)
            #pragma unroll
            for (int b = 0; b < 4; b++)
                #pragma unroll
                for (int c = 0; c < 4; c++) acc[a][b][c] = 0.0f;

        warp_gemm_cp(abase, bring, (const uint2*)g_pack + L*PACK_HIDW, HID,
                     wid*32, lane, acc);

        __syncthreads();            // all warps done READING plane
        const float* bs = bias_s + L*256;
        #pragma unroll
        for (int mt = 0; mt < 4; mt++){
            int rb = mt*16 + (lane >> 2);
            #pragma unroll
            for (int nt = 0; nt < 4; nt++){
                int cb = wid*32 + nt*8 + (lane & 3)*2;
                float bb0 = bs[cb], bb1 = bs[cb+1];
                float v0 = silu_f(acc[mt][nt][0] + bb0);
                float v1 = silu_f(acc[mt][nt][1] + bb1);
                *(uint32_t*)&pA[rb*APITCH + cb] = pack2h(v0, v1);
                float v2 = silu_f(acc[mt][nt][2] + bb0);
                float v3 = silu_f(acc[mt][nt][3] + bb1);
                *(uint32_t*)&pA[(rb+8)*APITCH + cb] = pack2h(v2, v3);
            }
        }
        __syncthreads();            // plane fully rewritten
    }

    // ---- head (256 -> 2695), fp16 1-term ----
    const uint2* Ph = (const uint2*)(g_pack + HID_U32);
    #pragma unroll 1
    for (int nc = 0; nc < 11; nc++){
        int nbase = nc*256 + wid*32;
        float acc[4][4][4];
        #pragma unroll
        for (int a = 0; a < 4; a++)
            #pragma unroll
            for (int b = 0; b < 4; b++)
                #pragma unroll
                for (int c = 0; c < 4; c++) acc[a][b][c] = 0.0f;

        warp_gemm_cp(abase, bring, Ph, NOUT, nbase, lane, acc);

        #pragma unroll
        for (int mt = 0; mt < 4; mt++){
            int rr = mt*16 + (lane >> 2);
            float l0 = scl[rr],   rv0 = scr[rr],   n0s = scn[rr];
            float l1 = scl[rr+8], rv1 = scr[rr+8], n1s = scn[rr+8];
            #pragma unroll
            for (int nt = 0; nt < 4; nt++){
                int cb = nbase + nt*8 + (lane & 3)*2;
                if (cb < NOUT){
                    float bb0 = bias_h[cb];
                    float s0 = hsel(cb, l0, rv0, n0s);
                    float s1 = hsel(cb, l1, rv1, n1s);
                    out[(size_t)(r0+rr)   * NOUT + cb] = (acc[mt][nt][0] + bb0) * s0;
                    out[(size_t)(r0+rr+8) * NOUT + cb] = (acc[mt][nt][2] + bb0) * s1;
                    if (cb + 1 < NOUT){
                        float bb1 = bias_h[cb+1];
                        float t0 = hsel(cb+1, l0, rv0, n0s);
                        float t1 = hsel(cb+1, l1, rv1, n1s);
                        out[(size_t)(r0+rr)   * NOUT + cb+1] = (acc[mt][nt][1] + bb1) * t0;
                        out[(size_t)(r0+rr+8) * NOUT + cb+1] = (acc[mt][nt][3] + bb1) * t1;
                    }
                }
            }
        }
    }
}

// ---------------- launch ----------------
#define SMEM_BYTES (8*4096 + MROWS*APITCH*2 + (MROWS*7 + 3*MROWS + 3*256 + 2696)*4)

extern "C" void kernel_launch(void* const* d_in, const int* in_sizes, int n_in,
                              void* d_out, int out_size)
{
    const float* x  = (const float*)d_in[0];
    const float* W0 = (const float*)d_in[1];
    const float* b0 = (const float*)d_in[2];
    const float* W1 = (const float*)d_in[3];
    const float* b1 = (const float*)d_in[4];
    const float* W2 = (const float*)d_in[5];
    const float* b2 = (const float*)d_in[6];
    const float* W3 = (const float*)d_in[7];
    const float* b3 = (const float*)d_in[8];
    const float* Wh = (const float*)d_in[9];
    const float* bh = (const float*)d_in[10];
    float* out = (float*)d_out;

    int B = in_sizes[0] / 7;

    cudaFuncSetAttribute(h3tcs_mma_kernel,
                         cudaFuncAttributeMaxDynamicSharedMemorySize, SMEM_BYTES);

    pack_weights<<<(PACK_N + 255)/256, 256>>>(W1, W2, W3, Wh);
    h3tcs_mma_kernel<<<B / MROWS, NTHREADS, SMEM_BYTES>>>(x, W0, b0, b1, b2, b3, bh, out);
}

// round 14
// speedup vs baseline: 1.7801x; 1.1802x over previous
#include <cuda_runtime.h>
#include <cuda_bf16.h>
#include <cuda_fp16.h>
#include <stdint.h>

// H3TCSNetwork, mma.sync path. R14 = R13 with:
//  - cp.async ring depth 6, wait distance 4 ksteps (covers ~430cyc L2@NAT)
//  - B repacked per 32-col chunk: lane-contiguous 16B slices -> 2x cp16 +
//    2x LDS.128 per kstep, conflict-free, fully coalesced, zero guards
//    (head padded to 2816 cols in the pack).

#define NTHREADS 256
#define MROWS    64
#define HID      256
#define NOUT     2695
#define APITCH   264                  // fp16 elems per smem plane row (528 B)

// packed layout: per (gemm,32-col chunk): 16 ksteps x 128 uint2 (1KB/kstep)
// chunk-blocks: 24 hidden (3 gemms x 8) + 88 head (2816/32) = 112
#define CB_HEAD0  24
#define PACK2_N   (112 * 2048)        // uint2 count = 229376 (1.75 MB)

__device__ uint2 g_pack2[PACK2_N];

// ---------------- helpers ----------------
__device__ __forceinline__ uint32_t smem_u32(const void* p){
    return (uint32_t)__cvta_generic_to_shared(p);
}
__device__ __forceinline__ uint32_t pack2h(float lo, float hi){
    uint32_t r;
    asm("cvt.rn.f16x2.f32 %0, %1, %2;" : "=r"(r) : "f"(hi), "f"(lo));
    return r;
}
__device__ __forceinline__ float silu_f(float v){
    return __fdividef(v, 1.0f + __expf(-v));
}
__device__ __forceinline__ void ldsm_x4(uint32_t a[4], uint32_t addr){
    asm volatile("ldmatrix.sync.aligned.m8n8.x4.shared.b16 {%0,%1,%2,%3}, [%4];"
                 : "=r"(a[0]), "=r"(a[1]), "=r"(a[2]), "=r"(a[3]) : "r"(addr));
}
__device__ __forceinline__ void mma_f16(float c[4], const uint32_t a[4],
                                        uint32_t b0, uint32_t b1){
    asm volatile("mma.sync.aligned.m16n8k16.row.col.f32.f16.f16.f32 "
                 "{%0,%1,%2,%3}, {%4,%5,%6,%7}, {%8,%9}, {%0,%1,%2,%3};"
                 : "+f"(c[0]), "+f"(c[1]), "+f"(c[2]), "+f"(c[3])
                 : "r"(a[0]), "r"(a[1]), "r"(a[2]), "r"(a[3]), "r"(b0), "r"(b1));
}
__device__ __forceinline__ void cp16(uint32_t dst, const void* src){
    asm volatile("cp.async.ca.shared.global [%0], [%1], 16;" :: "r"(dst), "l"(src));
}
#define CPC()  asm volatile("cp.async.commit_group;" ::: "memory")
#define CPW4() asm volatile("cp.async.wait_group 4;" ::: "memory")
__device__ __forceinline__ void lds128(uint4& v, uint32_t addr){
    asm volatile("ld.shared.v4.u32 {%0,%1,%2,%3}, [%4];"
                 : "=r"(v.x), "=r"(v.y), "=r"(v.z), "=r"(v.w) : "r"(addr));
}

// ---------------- weight pack kernel ----------------
// uint2 idx decode: cb = idx>>11; rem = idx&2047; s = rem>>7; pos = rem&127.
//   pos<64 : L = pos>>1, nt = pos&1
//   pos>=64: L = (pos-64)>>1, nt = 2 + ((pos-64)&1)
// q = L&3, nl = L>>2, k0 = s*16 + q*2, n = chunk*32 + nt*8 + nl.
// value = { f16x2(W[k0][n], W[k0+1][n]), f16x2(W[k0+8][n], W[k0+9][n]) }.
__global__ void pack_weights(const float* __restrict__ W1, const float* __restrict__ W2,
                             const float* __restrict__ W3, const float* __restrict__ Wh)
{
    int idx = blockIdx.x * blockDim.x + threadIdx.x;
    if (idx >= PACK2_N) return;
    int cb  = idx >> 11;
    int rem = idx & 2047;
    int s   = rem >> 7;
    int pos = rem & 127;
    int L, nt;
    if (pos < 64){ L = pos >> 1; nt = pos & 1; }
    else         { L = (pos - 64) >> 1; nt = 2 + ((pos - 64) & 1); }
    int q  = L & 3;
    int nl = L >> 2;
    int k0 = s * 16 + q * 2;
    int n_local = nt * 8 + nl;

    const float* W; int N; int n;
    if (cb < CB_HEAD0){
        int g = cb >> 3;
        W = (g == 0) ? W1 : (g == 1) ? W2 : W3;
        N = HID;
        n = (cb & 7) * 32 + n_local;
    } else {
        W = Wh; N = NOUT;
        n = (cb - CB_HEAD0) * 32 + n_local;
    }
    uint2 v = make_uint2(0, 0);
    if (n < N){
        v.x = pack2h(W[(size_t)k0     * N + n], W[(size_t)(k0+1) * N + n]);
        v.y = pack2h(W[(size_t)(k0+8) * N + n], W[(size_t)(k0+9) * N + n]);
    }
    g_pack2[idx] = v;
}

#define MMA4(accrow, a, bA, bB) \
    do { \
        mma_f16((accrow)[0], a, (bA).x, (bA).y); \
        mma_f16((accrow)[1], a, (bA).z, (bA).w); \
        mma_f16((accrow)[2], a, (bB).x, (bB).y); \
        mma_f16((accrow)[3], a, (bB).z, (bB).w); \
    } while(0)

#define RING_WARP 6144u      // 6 slots x 1024B per warp

// ------- warp GEMM: fp16 1-term, 64x32 tile, cp.async ring depth 6 ----------
// Prologue commits slots 0..4; body kstep s: wait_group 4 (completes slot s),
// read, MMA (A-pipelined), stage slot s+5, commit. Distance = 4 ksteps.
__device__ __forceinline__ void warp_gemm_cp(uint32_t abase, uint32_t bring,
                                             int cb, int lane, float acc[4][4][4])
{
    const char* src = (const char*)(g_pack2 + (size_t)cb * 2048);
    const uint32_t L16 = (uint32_t)lane * 16u;

    #pragma unroll
    for (int i = 0; i < 5; i++){
        cp16(bring + (uint32_t)i*1024u + L16,        src + L16);
        cp16(bring + (uint32_t)i*1024u + 512u + L16, src + 512u + L16);
        CPC();
        src += 1024;
    }

    const uint32_t MT = 16u*(APITCH*2);
    uint32_t a0[4], a1[4];
    ldsm_x4(a0, abase);                        // mt0, kstep 0

    int rslot = 0, wslot = 5;
    #pragma unroll 1
    for (int s = 0; s < 16; s++){
        CPW4();                                // slot s complete
        const uint32_t sa = bring + (uint32_t)rslot*1024u + L16;
        uint4 bA, bB;
        lds128(bA, sa);
        lds128(bB, sa + 512u);

        const uint32_t bs = abase + (uint32_t)s * 32u;
        ldsm_x4(a1, bs + MT);                  // mt1
        MMA4(acc[0], a0, bA, bB);
        ldsm_x4(a0, bs + 2*MT);                // mt2
        MMA4(acc[1], a1, bA, bB);
        ldsm_x4(a1, bs + 3*MT);                // mt3
        MMA4(acc[2], a0, bA, bB);
        ldsm_x4(a0, bs + 32u);                 // mt0, kstep s+1 (s=15: row pad, in-plane)
        MMA4(acc[3], a1, bA, bB);

        if (s < 11){                           // stage kstep s+5
            const uint32_t da = bring + (uint32_t)wslot*1024u + L16;
            cp16(da,        src + L16);
            cp16(da + 512u, src + 512u + L16);
            src += 1024;
        }
        CPC();                                 // commit (possibly empty) every kstep
        if (++rslot == 6) rslot = 0;
        if (++wslot == 6) wslot = 0;
    }
}

__device__ __forceinline__ float hsel(int col, float l, float r, float n){
    if (col < 1225) return 1.0f;
    if (col < 1715) return l;
    if (col < 2205) return r;
    return n;
}

// ---------------- main fused kernel ----------------
__global__ __launch_bounds__(NTHREADS, 2)
void h3tcs_mma_kernel(const float* __restrict__ x,
                      const float* __restrict__ W0, const float* __restrict__ b0,
                      const float* __restrict__ b1, const float* __restrict__ b2,
                      const float* __restrict__ b3, const float* __restrict__ bh,
                      float* __restrict__ out)
{
    extern __shared__ char smem[];
    char*   ringc = smem;                             // 8 warps * 6144B = 48KB
    __half* pA    = (__half*)(smem + 8*RING_WARP);    // fp16 activation plane
    float* xs     = (float*)(pA + MROWS*APITCH);
    float* scl    = xs  + MROWS*7;
    float* scr    = scl + MROWS;
    float* scn    = scr + MROWS;
    float* bias_s = scn + MROWS;                      // 3*256
    float* bias_h = bias_s + 3*256;                   // 2696

    const int tid  = threadIdx.x;
    const int lane = tid & 31;
    const int wid  = tid >> 5;
    const int r0   = blockIdx.x * MROWS;
    const uint32_t bring = smem_u32(ringc) + (uint32_t)wid * RING_WARP;

    for (int i = tid; i < MROWS*7; i += NTHREADS) xs[i] = x[(size_t)r0*7 + i];
    bias_s[tid]       = b1[tid];
    bias_s[256 + tid] = b2[tid];
    bias_s[512 + tid] = b3[tid];
    for (int i = tid; i < NOUT; i += NTHREADS) bias_h[i] = bh[i];
    __syncthreads();

    if (tid < MROWS){
        float lam = xs[tid*7];
        float s = 1.0f / (1.0f + __expf(lam * (-5.0f/0.15f)));
        scl[tid] = 1.0f - s;
        scr[tid] = s;
        float t = lam * 5.0f;
        scn[tid] = __expf(-t*t);
    }

    // ---- layer 0 (7 -> 256), fp32 FFMA, fp16 store ----
    {
        int j = tid;
        float w0r[7];
        #pragma unroll
        for (int k = 0; k < 7; k++) w0r[k] = W0[k*HID + j];
        float bj = b0[j];
        for (int r = 0; r < MROWS; r++){
            float v = bj;
            #pragma unroll
            for (int k = 0; k < 7; k++) v = fmaf(xs[r*7 + k], w0r[k], v);
            pA[r*APITCH + j] = __float2half(silu_f(v));
        }
    }
    __syncthreads();

    const int sub = lane >> 3;
    const int rowin = (lane & 7) + (sub & 1) * 8;
    const int colin = (sub >> 1) * 8;
    const uint32_t abase = smem_u32(pA) + ((uint32_t)rowin * APITCH + colin) * 2;

    // ---- hidden layers 1..3: fp16 1-term, m64n32 per warp ----
    #pragma unroll 1
    for (int L = 0; L < 3; L++){
        float acc[4][4][4];
        #pragma unroll
        for (int a = 0; a < 4; a++)
            #pragma unroll
            for (int b = 0; b < 4; b++)
                #pragma unroll
                for (int c = 0; c < 4; c++) acc[a][b][c] = 0.0f;

        warp_gemm_cp(abase, bring, L*8 + wid, lane, acc);

        __syncthreads();            // all warps done READING plane
        const float* bs = bias_s + L*256;
        #pragma unroll
        for (int mt = 0; mt < 4; mt++){
            int rb = mt*16 + (lane >> 2);
            #pragma unroll
            for (int nt = 0; nt < 4; nt++){
                int cb = wid*32 + nt*8 + (lane & 3)*2;
                float bb0 = bs[cb], bb1 = bs[cb+1];
                float v0 = silu_f(acc[mt][nt][0] + bb0);
                float v1 = silu_f(acc[mt][nt][1] + bb1);
                *(uint32_t*)&pA[rb*APITCH + cb] = pack2h(v0, v1);
                float v2 = silu_f(acc[mt][nt][2] + bb0);
                float v3 = silu_f(acc[mt][nt][3] + bb1);
                *(uint32_t*)&pA[(rb+8)*APITCH + cb] = pack2h(v2, v3);
            }
        }
        __syncthreads();            // plane fully rewritten
    }

    // ---- head (256 -> 2695 padded 2816), fp16 1-term ----
    #pragma unroll 1
    for (int nc = 0; nc < 11; nc++){
        float acc[4][4][4];
        #pragma unroll
        for (int a = 0; a < 4; a++)
            #pragma unroll
            for (int b = 0; b < 4; b++)
                #pragma unroll
                for (int c = 0; c < 4; c++) acc[a][b][c] = 0.0f;

        warp_gemm_cp(abase, bring, CB_HEAD0 + nc*8 + wid, lane, acc);

        int nbase = nc*256 + wid*32;
        #pragma unroll
        for (int mt = 0; mt < 4; mt++){
            int rr = mt*16 + (lane >> 2);
            float l0 = scl[rr],   rv0 = scr[rr],   n0s = scn[rr];
            float l1 = scl[rr+8], rv1 = scr[rr+8], n1s = scn[rr+8];
            #pragma unroll
            for (int nt = 0; nt < 4; nt++){
                int cb = nbase + nt*8 + (lane & 3)*2;
                if (cb < NOUT){
                    float bb0 = bias_h[cb];
                    float s0 = hsel(cb, l0, rv0, n0s);
                    float s1 = hsel(cb, l1, rv1, n1s);
                    out[(size_t)(r0+rr)   * NOUT + cb] = (acc[mt][nt][0] + bb0) * s0;
                    out[(size_t)(r0+rr+8) * NOUT + cb] = (acc[mt][nt][2] + bb0) * s1;
                    if (cb + 1 < NOUT){
                        float bb1 = bias_h[cb+1];
                        float t0 = hsel(cb+1, l0, rv0, n0s);
                        float t1 = hsel(cb+1, l1, rv1, n1s);
                        out[(size_t)(r0+rr)   * NOUT + cb+1] = (acc[mt][nt][1] + bb1) * t0;
                        out[(size_t)(r0+rr+8) * NOUT + cb+1] = (acc[mt][nt][3] + bb1) * t1;
                    }
                }
            }
        }
    }
}

// ---------------- launch ----------------
#define SMEM_BYTES (8*RING_WARP + MROWS*APITCH*2 + (MROWS*7 + 3*MROWS + 3*256 + 2696)*4)

extern "C" void kernel_launch(void* const* d_in, const int* in_sizes, int n_in,
                              void* d_out, int out_size)
{
    const float* x  = (const float*)d_in[0];
    const float* W0 = (const float*)d_in[1];
    const float* b0 = (const float*)d_in[2];
    const float* W1 = (const float*)d_in[3];
    const float* b1 = (const float*)d_in[4];
    const float* W2 = (const float*)d_in[5];
    const float* b2 = (const float*)d_in[6];
    const float* W3 = (const float*)d_in[7];
    const float* b3 = (const float*)d_in[8];
    const float* Wh = (const float*)d_in[9];
    const float* bh = (const float*)d_in[10];
    float* out = (float*)d_out;

    int B = in_sizes[0] / 7;

    cudaFuncSetAttribute(h3tcs_mma_kernel,
                         cudaFuncAttributeMaxDynamicSharedMemorySize, SMEM_BYTES);

    pack_weights<<<(PACK2_N + 255)/256, 256>>>(W1, W2, W3, Wh);
    h3tcs_mma_kernel<<<B / MROWS, NTHREADS, SMEM_BYTES>>>(x, W0, b0, b1, b2, b3, bh, out);
}